// round 15
// baseline (speedup 1.0000x reference)
#include <cuda_runtime.h>
#include <cuda_fp16.h>
#include <cstdint>

// ---------------------------------------------------------------------------
// Problem constants
// ---------------------------------------------------------------------------
#define NROWS_MAX 100000
#define CONCAT    352
#define NODE_DIM  128
#define EQUI_DIM  480
#define OUT_DIM   608

// Fragment-ordered packed weights: for iteration it (0..43: 22 W1 + 22 W2),
// warp-column wn (0..3), vec j4 (0..5), lane (0..31): one uint4 = 4 half2
// words w = j4*4+m. Word w<22: nt=w>>1, b01=w&1 ->
//   half2( W[2*k2][n], W[2*k2+1][n] ),  k2 = itk*8 + (lane&3) + b01*4,
//   n = wn*88 + (w>>1)*8 + (lane>>2).  Words 22,23 = 0 padding.
// Per warp-iteration: 6 coalesced LDG.128 deliver the full B fragment set.
__device__ uint32_t g_wfrag[(size_t)44 * 4 * 6 * 32 * 4];   // 2.16 MB

// ---------------------------------------------------------------------------
// PTX helpers (sm_90-era baseline only; tcgen05 rejected by this toolchain)
// ---------------------------------------------------------------------------
__device__ __forceinline__ uint32_t smem_to_u32(const void* p) {
    uint32_t a;
    asm("{ .reg .u64 t; cvta.to.shared.u64 t, %1; cvt.u32.u64 %0, t; }" : "=r"(a) : "l"(p));
    return a;
}

__device__ __forceinline__ void mma_fp16(float* d, const uint32_t* a, uint32_t b0, uint32_t b1) {
    asm volatile(
        "mma.sync.aligned.m16n8k16.row.col.f32.f16.f16.f32 "
        "{%0,%1,%2,%3}, {%4,%5,%6,%7}, {%8,%9}, {%0,%1,%2,%3};\n"
        : "+f"(d[0]), "+f"(d[1]), "+f"(d[2]), "+f"(d[3])
        : "r"(a[0]), "r"(a[1]), "r"(a[2]), "r"(a[3]), "r"(b0), "r"(b1));
}

__device__ __forceinline__ void ldsm_a4(uint32_t* r, uint32_t addr) {
    asm volatile("ldmatrix.sync.aligned.m8n8.x4.shared.b16 {%0,%1,%2,%3}, [%4];"
        : "=r"(r[0]), "=r"(r[1]), "=r"(r[2]), "=r"(r[3]) : "r"(addr));
}

// ---------------------------------------------------------------------------
// Kernel 0: pack W1/W2 into fragment order (see g_wfrag comment).
// 176 blocks = (it*4 + wn); 256 threads handle 6*32*4 = 768 half2 words.
// ---------------------------------------------------------------------------
__global__ void pack_kernel(const float* __restrict__ W1, const float* __restrict__ W2) {
    int b = blockIdx.x;
    int it = b >> 2, wn = b & 3;
    int itk = (it < 22) ? it : it - 22;
    const float* Wsrc = (it < 22) ? W1 : W2;
    uint32_t* dst = g_wfrag + (size_t)b * 768;
    for (int i = threadIdx.x; i < 768; i += 256) {
        int j4 = i >> 7, rem = i & 127;
        int lane = rem >> 2, m = rem & 3;
        int w = j4 * 4 + m;
        uint32_t val = 0;
        if (w < 22) {
            int nt = w >> 1, b01 = w & 1;
            int q = lane >> 2, kq = lane & 3;
            int n = wn * 88 + nt * 8 + q;
            int k2 = itk * 8 + kq + b01 * 4;
            __half2 h = __floats2half2_rn(Wsrc[(size_t)(2 * k2) * CONCAT + n],
                                          Wsrc[(size_t)(2 * k2 + 1) * CONCAT + n]);
            val = *(uint32_t*)&h;
        }
        dst[(j4 * 32 + lane) * 4 + m] = val;
    }
}

// ---------------------------------------------------------------------------
// Fused kernel: norm prologue + MLP + gated epilogue.
// 64-row CTAs, 256 threads (8 warps, 2M x 4N, warp tile 32x88), 2 CTAs/SM.
// A (64x352 fp16, row stride 720 B) built in smem by the norm prologue and
// read via ldmatrix. B fragments: 6 coalesced LDG.128 per warp-iteration from
// g_wfrag (L2-resident). NO smem ring, NO mainloop barriers, no producer.
//
// smem bytes:
//   bias  @0     : 704 f32             (2816)
//   stats @2816  : 64*4 f32            (1024)  -> 3840
//   A     @3840  : 64*180 words        (46080) -> 49920
//   G overlay @3840 : 64*356 f32       (91136) -> 94976 (post-loop, safe)
// total 94976 B/CTA -> 2 CTAs/SM
// ---------------------------------------------------------------------------
#define SM_STATS_F 704
#define SM_A_B     3840
#define SMEM_TOTAL 94976
#define SM_G_F     960          // float index of G overlay (3840/4)

__global__ __launch_bounds__(256, 2) void mlp_kernel(
    const float* __restrict__ b1, const float* __restrict__ b2,
    const float* __restrict__ lnw, const float* __restrict__ lnb,
    const float* __restrict__ nsc, const float* __restrict__ neq,
    float* __restrict__ out, int N)
{
    extern __shared__ char smc[];
    float* smf = (float*)smc;
    uint32_t sb = smem_to_u32(smc);
    const int tid = threadIdx.x, lane = tid & 31, wid = tid >> 5;
    const int wm = wid >> 2, wn = wid & 3;          // 2 x 4 warp grid
    const int rowBase = blockIdx.x * 64;

    uint32_t* Aw = (uint32_t*)(smc + SM_A_B);

    for (int i = tid; i < 704; i += 256)
        smf[i] = (i < CONCAT) ? b1[i] : b2[i - CONCAT];

    // ---------------- norm prologue: 8 rows per warp ----------------
    {
        const float4 lw4 = *(const float4*)&lnw[lane * 4];
        const float4 lb4 = *(const float4*)&lnb[lane * 4];
#pragma unroll 2
        for (int pass = 0; pass < 8; ++pass) {
            int rr = wid * 8 + pass;
            int gr = rowBase + rr;
            float4 xv = make_float4(0.f, 0.f, 0.f, 0.f);
            float4 ev = make_float4(0.f, 0.f, 0.f, 0.f);
            float a0 = 0.f, a1 = 0.f, a2 = 0.f, a3 = 0.f, a4 = 0.f, a5 = 0.f;
            float q0 = 0.f, q1 = 0.f, q2 = 0.f, q3 = 0.f, q4 = 0.f;
            if (gr < N) {
                const float* xs = nsc + (size_t)gr * NODE_DIM;
                const float* xe = neq + (size_t)gr * EQUI_DIM;
                xv = *(const float4*)&xs[lane * 4];
                ev = *(const float4*)&xe[lane * 4];
                const float* l1p = &xe[128 + 6 * lane];
                a0 = l1p[0]; a1 = l1p[1]; a2 = l1p[2];
                a3 = l1p[3]; a4 = l1p[4]; a5 = l1p[5];
                const float* l2p = &xe[320 + 5 * lane];
                q0 = l2p[0]; q1 = l2p[1]; q2 = l2p[2]; q3 = l2p[3]; q4 = l2p[4];
            }
            float s1a = a0 * a0 + a1 * a1 + a2 * a2;
            float s1b = a3 * a3 + a4 * a4 + a5 * a5;
            float s2  = q0 * q0 + q1 * q1 + q2 * q2 + q3 * q3 + q4 * q4;

            float sx  = xv.x + xv.y + xv.z + xv.w;
            float sxx = xv.x * xv.x + xv.y * xv.y + xv.z * xv.z + xv.w * xv.w;
            float se  = ev.x + ev.y + ev.z + ev.w;
            float se2 = ev.x * ev.x + ev.y * ev.y + ev.z * ev.z + ev.w * ev.w;
            float ssl1 = s1a + s1b;
            float ssl2 = s2;
#pragma unroll
            for (int o = 16; o > 0; o >>= 1) {
                sx   += __shfl_xor_sync(~0u, sx, o);
                sxx  += __shfl_xor_sync(~0u, sxx, o);
                se   += __shfl_xor_sync(~0u, se, o);
                se2  += __shfl_xor_sync(~0u, se2, o);
                ssl1 += __shfl_xor_sync(~0u, ssl1, o);
                ssl2 += __shfl_xor_sync(~0u, ssl2, o);
            }
            float mu  = sx * (1.f / 128.f);
            float var = sxx * (1.f / 128.f) - mu * mu;
            float rs  = rsqrtf(var + 1e-5f);
            float m0  = se * (1.f / 128.f);
            float sc2m = se2 * (1.f / 128.f) - m0 * m0;
            float r0 = rsqrtf(sc2m + 1e-5f);
            float r1 = rsqrtf(ssl1 * (1.f / 64.f) + 1e-5f);
            float r2 = rsqrtf(ssl2 * (1.f / 32.f) + 1e-5f);

            uint32_t* Arow = Aw + rr * 180;
            {
                float f0 = (xv.x - mu) * rs * lw4.x + lb4.x;
                float f1 = (xv.y - mu) * rs * lw4.y + lb4.y;
                float f2 = (xv.z - mu) * rs * lw4.z + lb4.z;
                float f3 = (xv.w - mu) * rs * lw4.w + lb4.w;
                __half2 p0 = __floats2half2_rn(f0, f1);
                __half2 p1 = __floats2half2_rn(f2, f3);
                Arow[lane * 2] = *(uint32_t*)&p0;
                Arow[lane * 2 + 1] = *(uint32_t*)&p1;
            }
            {
                float g0 = (ev.x - m0) * r0, g1 = (ev.y - m0) * r0;
                float g2 = (ev.z - m0) * r0, g3 = (ev.w - m0) * r0;
                __half2 p0 = __floats2half2_rn(g0 * g0, g1 * g1);
                __half2 p1 = __floats2half2_rn(g2 * g2, g3 * g3);
                Arow[64 + lane * 2] = *(uint32_t*)&p0;
                Arow[64 + lane * 2 + 1] = *(uint32_t*)&p1;
            }
            {
                float v0 = s1a * r1 * r1 * 0.57735026918962576451f;
                float v1 = s1b * r1 * r1 * 0.57735026918962576451f;
                __half2 p = __floats2half2_rn(v0, v1);
                Arow[128 + lane] = *(uint32_t*)&p;
            }
            {
                float v = s2 * r2 * r2 * 0.44721359549995793928f;
                float vhi = __shfl_down_sync(~0u, v, 1);
                if (!(lane & 1)) {
                    __half2 p = __floats2half2_rn(v, vhi);
                    Arow[160 + (lane >> 1)] = *(uint32_t*)&p;
                }
            }
            if (lane == 0)
                *(float4*)&smf[SM_STATS_F + rr * 4] = make_float4(m0, r0, r1, r2);
        }
    }
    __syncthreads();   // A tile + stats + bias complete

    float acc[2][11][4];
#pragma unroll
    for (int mt = 0; mt < 2; mt++)
#pragma unroll
        for (int nt = 0; nt < 11; nt++)
#pragma unroll
            for (int e = 0; e < 4; e++) acc[mt][nt][e] = 0.f;

    // ldmatrix A lane address (g8 = lane/8, l8 = lane%8)
    const int g8 = lane >> 3, l8 = lane & 7;
    const int q = lane >> 2, kq = lane & 3;
    const uint32_t aLane = sb + SM_A_B +
        (uint32_t)((wm * 32 + (g8 & 1) * 8 + l8) * 720 + (g8 >> 1) * 16);

    // B fragment stream: 6 uint4 per iteration, iteration stride 768 uint4.
    const uint4* __restrict__ wfp =
        (const uint4*)g_wfrag + (size_t)wn * 6 * 32 + lane;

    // 44 iterations of K=16: 0..21 = GEMM1, 22..43 = GEMM2. No barriers.
#pragma unroll 1
    for (int it = 0; it < 44; ++it) {
        if (it == 22) {
            // epilogue 1: H = fp16(silu(D1 + b1)) overwrites A in place.
            __syncthreads();   // all warps done reading A for GEMM1
#pragma unroll
            for (int mt = 0; mt < 2; mt++) {
                int r0 = wm * 32 + mt * 16 + q;
#pragma unroll
                for (int nt = 0; nt < 11; nt++) {
                    int c = wn * 88 + nt * 8 + 2 * kq;
                    int c2 = c >> 1;
                    float h0 = acc[mt][nt][0] + smf[c];
                    float h1 = acc[mt][nt][1] + smf[c + 1];
                    float h2 = acc[mt][nt][2] + smf[c];
                    float h3 = acc[mt][nt][3] + smf[c + 1];
                    h0 = __fdividef(h0, 1.f + __expf(-h0));
                    h1 = __fdividef(h1, 1.f + __expf(-h1));
                    h2 = __fdividef(h2, 1.f + __expf(-h2));
                    h3 = __fdividef(h3, 1.f + __expf(-h3));
                    __half2 p01 = __floats2half2_rn(h0, h1);
                    __half2 p23 = __floats2half2_rn(h2, h3);
                    Aw[r0 * 180 + c2] = *(uint32_t*)&p01;
                    Aw[(r0 + 8) * 180 + c2] = *(uint32_t*)&p23;
                    acc[mt][nt][0] = 0.f; acc[mt][nt][1] = 0.f;
                    acc[mt][nt][2] = 0.f; acc[mt][nt][3] = 0.f;
                }
            }
            __syncthreads();   // H visible to all warps
        }

        // self-service B fragments: 6 coalesced LDG.128 (MLP = 6)
        uint4 v0 = wfp[0];
        uint4 v1 = wfp[32];
        uint4 v2 = wfp[64];
        uint4 v3 = wfp[96];
        uint4 v4 = wfp[128];
        uint4 v5 = wfp[160];
        wfp += 768;

        const int itk = (it < 22) ? it : it - 22;
        uint32_t a0[4], a1[4];
        ldsm_a4(a0, aLane + itk * 32);
        ldsm_a4(a1, aLane + 11520 + itk * 32);       // +16 rows * 720 B

        mma_fp16(acc[0][0], a0, v0.x, v0.y);  mma_fp16(acc[1][0], a1, v0.x, v0.y);
        mma_fp16(acc[0][1], a0, v0.z, v0.w);  mma_fp16(acc[1][1], a1, v0.z, v0.w);
        mma_fp16(acc[0][2], a0, v1.x, v1.y);  mma_fp16(acc[1][2], a1, v1.x, v1.y);
        mma_fp16(acc[0][3], a0, v1.z, v1.w);  mma_fp16(acc[1][3], a1, v1.z, v1.w);
        mma_fp16(acc[0][4], a0, v2.x, v2.y);  mma_fp16(acc[1][4], a1, v2.x, v2.y);
        mma_fp16(acc[0][5], a0, v2.z, v2.w);  mma_fp16(acc[1][5], a1, v2.z, v2.w);
        mma_fp16(acc[0][6], a0, v3.x, v3.y);  mma_fp16(acc[1][6], a1, v3.x, v3.y);
        mma_fp16(acc[0][7], a0, v3.z, v3.w);  mma_fp16(acc[1][7], a1, v3.z, v3.w);
        mma_fp16(acc[0][8], a0, v4.x, v4.y);  mma_fp16(acc[1][8], a1, v4.x, v4.y);
        mma_fp16(acc[0][9], a0, v4.z, v4.w);  mma_fp16(acc[1][9], a1, v4.z, v4.w);
        mma_fp16(acc[0][10], a0, v5.x, v5.y); mma_fp16(acc[1][10], a1, v5.x, v5.y);
    }

    // epilogue 2: G = D2 + b2 (f32) overlays A (all reads done)
    __syncthreads();
#pragma unroll
    for (int mt = 0; mt < 2; mt++) {
        int r0 = wm * 32 + mt * 16 + q;
#pragma unroll
        for (int nt = 0; nt < 11; nt++) {
            int c = wn * 88 + nt * 8 + 2 * kq;
            float* G0 = smf + SM_G_F + r0 * 356;
            float* G1 = smf + SM_G_F + (r0 + 8) * 356;
            *(float2*)&G0[c] = make_float2(acc[mt][nt][0] + smf[352 + c],
                                           acc[mt][nt][1] + smf[352 + c + 1]);
            *(float2*)&G1[c] = make_float2(acc[mt][nt][2] + smf[352 + c],
                                           acc[mt][nt][3] + smf[352 + c + 1]);
        }
    }
    __syncthreads();

    // final epilogue: coalesced gated outputs (608 cols = 152 float4 per row)
    // 64*152 = 9728 = 38 * 256 exactly.
#pragma unroll 2
    for (int j = 0; j < 38; ++j) {
        int i = j * 256 + tid;
        int rr = i / 152, seg = i % 152;
        int gr = rowBase + rr;
        if (gr >= N) continue;
        int oc = seg * 4;
        const float4 st = *(const float4*)&smf[SM_STATS_F + rr * 4]; // m0,r0,r1,r2
        const float* G = smf + SM_G_F + rr * 356;
        float4 o;
        if (oc < 128) {
            float4 x = *(const float4*)&nsc[(size_t)gr * NODE_DIM + oc];
            const float4 g4 = *(const float4*)&G[oc];
            o.x = x.x + g4.x; o.y = x.y + g4.y; o.z = x.z + g4.z; o.w = x.w + g4.w;
        } else if (oc < 256) {
            int gi = oc - 128;
            float4 ne = *(const float4*)&neq[(size_t)gr * EQUI_DIM + gi];
            const float4 g4 = *(const float4*)&G[oc];
            o.x = ne.x + (ne.x - st.x) * st.y * g4.x;
            o.y = ne.y + (ne.y - st.x) * st.y * g4.y;
            o.z = ne.z + (ne.z - st.x) * st.y * g4.z;
            o.w = ne.w + (ne.w - st.x) * st.y * g4.w;
        } else if (oc < 448) {
            int pos = oc - 256;
            float4 ne = *(const float4*)&neq[(size_t)gr * EQUI_DIM + 128 + pos];
            o.x = ne.x * (1.f + st.z * G[256 + (pos    ) / 3]);
            o.y = ne.y * (1.f + st.z * G[256 + (pos + 1) / 3]);
            o.z = ne.z * (1.f + st.z * G[256 + (pos + 2) / 3]);
            o.w = ne.w * (1.f + st.z * G[256 + (pos + 3) / 3]);
        } else {
            int pos = oc - 448;
            float4 ne = *(const float4*)&neq[(size_t)gr * EQUI_DIM + 320 + pos];
            o.x = ne.x * (1.f + st.w * G[320 + (pos    ) / 5]);
            o.y = ne.y * (1.f + st.w * G[320 + (pos + 1) / 5]);
            o.z = ne.z * (1.f + st.w * G[320 + (pos + 2) / 5]);
            o.w = ne.w * (1.f + st.w * G[320 + (pos + 3) / 5]);
        }
        *(float4*)&out[(size_t)gr * OUT_DIM + oc] = o;
    }
}

// ---------------------------------------------------------------------------
// Launcher
// ---------------------------------------------------------------------------
extern "C" void kernel_launch(void* const* d_in, const int* in_sizes, int n_in,
                              void* d_out, int out_size)
{
    const float* nsc = (const float*)d_in[0];
    const float* neq = (const float*)d_in[1];
    const float* lnw = (const float*)d_in[2];
    const float* lnb = (const float*)d_in[3];
    const float* W1  = (const float*)d_in[4];
    const float* b1  = (const float*)d_in[5];
    const float* W2  = (const float*)d_in[6];
    const float* b2  = (const float*)d_in[7];
    float* out = (float*)d_out;

    int N = in_sizes[0] / NODE_DIM;

    cudaFuncSetAttribute(mlp_kernel, cudaFuncAttributeMaxDynamicSharedMemorySize, SMEM_TOTAL);

    pack_kernel<<<176, 256>>>(W1, W2);

    int ctas = (N + 63) / 64;
    mlp_kernel<<<ctas, 256, SMEM_TOTAL>>>(b1, b2, lnw, lnb, nsc, neq, out, N);
}